// round 1
// baseline (speedup 1.0000x reference)
#include <cuda_runtime.h>
#include <math.h>

#define DEV __device__ __forceinline__

// ---------------- problem constants ----------------
constexpr int Lx = 2048, Bc = 8, Dd = 1024, Zz = 128, Hh = 2048, Nn = 16;
constexpr int ROWS = Lx * Bc;                 // 16384
constexpr int NMX  = Dd + Zz + Hh + Dd;       // 4224
constexpr int NC   = 16, CL = Lx / NC;        // 16 chunks x 128 steps
constexpr float LAP_MU  = 0.707107f;
// 1 / (sigma * sqrt(2))
constexpr float LAP_INV = 1.0f / (0.282095f * 1.41421356237f);

// ---------------- device scratch (no allocs allowed) ----------------
__device__ float g_xn  [ROWS * Dd];           //  64 MB
__device__ float g_mx  [ROWS * Dd];           //  64 MB
__device__ float g_v   [ROWS * Hh];           // 128 MB
__device__ float g_u   [ROWS * Dd];           //  64 MB
__device__ float g_hx  [ROWS * Dd];           //  64 MB
__device__ float g_r   [ROWS * Hh];           // 128 MB
__device__ float g_q   [Bc * Lx * Zz];        //   8 MB
__device__ float g_k   [Bc * Lx * Zz];        //   8 MB
__device__ float g_attn[Bc * Lx * Lx];        // 128 MB
__device__ float g_hatt[Bc * Lx * Hh];        // 128 MB
__device__ float g_eq   [Nn * Dd];
__device__ float g_ew   [Nn * Dd];
__device__ float g_eq128[Nn * Dd];
__device__ float g_send [Bc * Dd * NC * Nn];  // 8 MB
__device__ float g_carry[Bc * Dd * NC * Nn];  // 8 MB

DEV float sigm(float x)  { return 1.0f / (1.0f + expf(-x)); }
DEV float silu(float x)  { return x / (1.0f + expf(-x)); }

// ---------------- layernorm: one block per (l,b) row ----------------
__global__ void ln_kernel(const float* __restrict__ x,
                          const float* __restrict__ w,
                          const float* __restrict__ b)
{
    int row = blockIdx.x;
    const float4* xr = reinterpret_cast<const float4*>(x + (size_t)row * Dd);
    float4 v = xr[threadIdx.x];                         // 256 thr * 4 = 1024
    float s  = v.x + v.y + v.z + v.w;
    float s2 = v.x*v.x + v.y*v.y + v.z*v.z + v.w*v.w;
    #pragma unroll
    for (int o = 16; o; o >>= 1) {
        s  += __shfl_xor_sync(0xffffffffu, s,  o);
        s2 += __shfl_xor_sync(0xffffffffu, s2, o);
    }
    __shared__ float sh[16];
    int warp = threadIdx.x >> 5, lane = threadIdx.x & 31;
    if (lane == 0) { sh[warp] = s; sh[8 + warp] = s2; }
    __syncthreads();
    float S = 0.f, S2 = 0.f;
    #pragma unroll
    for (int i = 0; i < 8; i++) { S += sh[i]; S2 += sh[8 + i]; }
    float mu  = S * (1.0f / Dd);
    float var = S2 * (1.0f / Dd) - mu * mu;
    float rs  = rsqrtf(var + 1e-5f);
    float4 wv = reinterpret_cast<const float4*>(w)[threadIdx.x];
    float4 bv = reinterpret_cast<const float4*>(b)[threadIdx.x];
    float4 o;
    o.x = (v.x - mu) * rs * wv.x + bv.x;
    o.y = (v.y - mu) * rs * wv.y + bv.y;
    o.z = (v.z - mu) * rs * wv.z + bv.z;
    o.w = (v.w - mu) * rs * wv.w + bv.w;
    reinterpret_cast<float4*>(g_xn + (size_t)row * Dd)[threadIdx.x] = o;
}

// ---------------- EMA parameter precompute ----------------
__global__ void ema_pre(const float* __restrict__ delta, const float* __restrict__ alpha,
                        const float* __restrict__ beta,  const float* __restrict__ gamma)
{
    int i = blockIdx.x * 256 + threadIdx.x;
    if (i >= Dd * Nn) return;
    int d = i / Nn, n = i % Nn;
    float p = sigm(delta[i]);
    float q = 1.0f - p * sigm(alpha[i]);
    float w = p * beta[i] * gamma[i] * 0.25f;   // 1/sqrt(N), N=16
    float qq = q;
    #pragma unroll
    for (int t = 0; t < 7; t++) qq *= qq;       // q^128
    g_eq   [n * Dd + d] = q;
    g_ew   [n * Dd + d] = w;
    g_eq128[n * Dd + d] = qq;
}

// ---------------- EMA chunked scan: pass A (local end-states) ----------------
__global__ void ema_scanA()
{
    int g = blockIdx.x * 256 + threadIdx.x;     // Bc*Dd*NC threads
    int d = g & (Dd - 1);
    int rest = g >> 10;
    int b = rest & (Bc - 1);
    int c = rest >> 3;
    float q[Nn], s[Nn];
    #pragma unroll
    for (int n = 0; n < Nn; n++) { q[n] = g_eq[n * Dd + d]; s[n] = 0.f; }
    const float* xp = g_xn + ((size_t)(c * CL) * Bc + b) * Dd + d;
    const size_t stride = (size_t)Bc * Dd;
    for (int i = 0; i < CL; i++) {
        float xv = xp[i * stride];
        #pragma unroll
        for (int n = 0; n < Nn; n++) s[n] = fmaf(q[n], s[n], xv);
    }
    float* o = g_send + ((size_t)(b * Dd + d) * NC + c) * Nn;
    #pragma unroll
    for (int n = 0; n < Nn; n++) o[n] = s[n];
}

// ---------------- pass B (chunk-level carries) ----------------
__global__ void ema_scanB()
{
    int g = blockIdx.x * 256 + threadIdx.x;     // Bc*Dd*Nn threads
    int n = g & (Nn - 1);
    int rest = g >> 4;
    int d = rest & (Dd - 1);
    int b = rest >> 10;
    float q128 = g_eq128[n * Dd + d];
    size_t base = (size_t)(b * Dd + d) * NC * Nn + n;
    float cur = 0.f;
    for (int c = 0; c < NC; c++) {
        g_carry[base + (size_t)c * Nn] = cur;
        cur = fmaf(q128, cur, g_send[base + (size_t)c * Nn]);
    }
}

// ---------------- pass C (final scan + silu output) ----------------
__global__ void ema_scanC(const float* __restrict__ omega)
{
    int g = blockIdx.x * 256 + threadIdx.x;
    int d = g & (Dd - 1);
    int rest = g >> 10;
    int b = rest & (Bc - 1);
    int c = rest >> 3;
    float q[Nn], w[Nn], s[Nn];
    const float* cp = g_carry + ((size_t)(b * Dd + d) * NC + c) * Nn;
    #pragma unroll
    for (int n = 0; n < Nn; n++) {
        q[n] = g_eq[n * Dd + d];
        w[n] = g_ew[n * Dd + d];
        s[n] = cp[n];
    }
    float om = omega[d];
    const size_t stride = (size_t)Bc * Dd;
    const float* xp = g_xn + ((size_t)(c * CL) * Bc + b) * Dd + d;
    float*       mp = g_mx + ((size_t)(c * CL) * Bc + b) * Dd + d;
    for (int i = 0; i < CL; i++) {
        float xv = xp[i * stride];
        #pragma unroll
        for (int n = 0; n < Nn; n++) s[n] = fmaf(q[n], s[n], xv);
        float o0 = 0.f, o1 = 0.f, o2 = 0.f, o3 = 0.f;
        #pragma unroll
        for (int n = 0; n < Nn; n++) {
            float t = w[n] * s[n];
            if ((n & 3) == 0) o0 += t; else if ((n & 3) == 1) o1 += t;
            else if ((n & 3) == 2) o2 += t; else o3 += t;
        }
        float val = (o0 + o1) + (o2 + o3) + xv * om;
        mp[i * stride] = silu(val);
    }
}

// ---------------- generic 128x128 tiled SGEMM ----------------
constexpr int BM = 128, BN = 128, BK = 16, TM = 8, TN = 8;   // 256 threads

// ---- A loaders (row-major, K contiguous) ----
struct ALxn {
    DEV float4 ld(int, int row, int k) const {
        return *reinterpret_cast<const float4*>(g_xn + (size_t)row * Dd + k);
    }
};
struct ALmx {
    DEV float4 ld(int, int row, int k) const {
        return *reinterpret_cast<const float4*>(g_mx + (size_t)row * Dd + k);
    }
};
struct ALq {
    DEV float4 ld(int bz, int row, int k) const {
        return *reinterpret_cast<const float4*>(g_q + ((size_t)bz * Lx + row) * Zz + k);
    }
};
struct ALattn {
    DEV float4 ld(int bz, int row, int k) const {
        return *reinterpret_cast<const float4*>(g_attn + ((size_t)bz * Lx + row) * Lx + k);
    }
};
struct ALhr {   // fused h * r on load; row = l*Bc + b
    DEV float4 ld(int, int row, int k) const {
        int l = row >> 3, b = row & 7;
        float4 hv = *reinterpret_cast<const float4*>(g_hatt + ((size_t)b * Lx + l) * Hh + k);
        float4 rv = *reinterpret_cast<const float4*>(g_r + (size_t)row * Hh + k);
        return make_float4(hv.x * rv.x, hv.y * rv.y, hv.z * rv.z, hv.w * rv.w);
    }
};

// ---- B loaders ----
struct BLnn {   // plain row-major K x N (weights)
    const float* B; int ldb;
    static constexpr bool kTrans = false;
    DEV float4 ld(int, int k, int n) const {
        return *reinterpret_cast<const float4*>(B + (size_t)k * ldb + n);
    }
};
struct BLkT {   // B = k (N x K, K contiguous) -> transposed access
    static constexpr bool kTrans = true;
    DEV float4 ld(int bz, int nrow, int k) const {
        return *reinterpret_cast<const float4*>(g_k + ((size_t)bz * Lx + nrow) * Zz + k);
    }
};
struct BLv {    // B[m,h] = v[(m*Bc + bz)*Hh + h]
    static constexpr bool kTrans = false;
    DEV float4 ld(int bz, int k, int n) const {
        return *reinterpret_cast<const float4*>(g_v + ((size_t)k * Bc + bz) * Hh + n);
    }
};

// ---- epilogues ----
struct EPv {
    const float* vb;
    DEV void store(int, int row, int col, float a) const {
        g_v[(size_t)row * Hh + col] = silu(a + vb[col]);
    }
};
struct EPmx {   // router: u | z->q,k | r | hx
    const float* mxb; const float* qg; const float* qb;
    DEV void store(int, int row, int col, float a) const {
        float val = a + mxb[col];
        if (col < Dd) {
            g_u[(size_t)row * Dd + col] = sigm(val);
        } else if (col < Dd + Zz) {
            int z = col - Dd;
            float s = silu(val);
            int l = row >> 3, b = row & 7;
            size_t o = ((size_t)b * Lx + l) * Zz + z;
            g_q[o] = s * qg[z]      + qb[z];
            g_k[o] = s * qg[Zz + z] + qb[Zz + z];
        } else if (col < Dd + Zz + Hh) {
            g_r[(size_t)row * Hh + (col - Dd - Zz)] = silu(val);
        } else {
            g_hx[(size_t)row * Dd + (col - Dd - Zz - Hh)] = val;
        }
    }
};
struct EPqk {
    const float* rel;
    DEV void store(int bz, int l, int m, float a) const {
        float x = a * (1.0f / (float)Lx) + rel[2047 + m - l];
        g_attn[((size_t)bz * Lx + l) * Lx + m] =
            0.5f * (1.0f + erff((x - LAP_MU) * LAP_INV));
    }
};
struct EPav {
    DEV void store(int bz, int l, int h, float a) const {
        g_hatt[((size_t)bz * Lx + l) * Hh + h] = a;
    }
};
struct EPf {
    const float* hb; const float* x; float* out;
    DEV void store(int, int row, int col, float a) const {
        size_t o = (size_t)row * Dd + col;
        float hval = silu(g_hx[o] + a + hb[col]);
        float xv = x[o];
        out[o] = xv + g_u[o] * (hval - xv);
    }
};

template <class AL, class BL, class EP>
__global__ __launch_bounds__(256)
void gemm_k(AL al, BL bl, EP ep, int K)
{
    __shared__ float As[BK][BM];
    __shared__ float Bs[BK][BN];
    int tid = threadIdx.x;
    int bz = blockIdx.z;
    int m0 = blockIdx.y * BM;
    int n0 = blockIdx.x * BN;
    int tx = tid & 15, ty = tid >> 4;

    float acc[TM][TN] = {};

    for (int kt = 0; kt < K; kt += BK) {
        // A tile: 128x16, stored transposed As[k][m]
        #pragma unroll
        for (int i = 0; i < 2; i++) {
            int f = tid + i * 256;
            int r = f >> 2, c4 = (f & 3) * 4;
            float4 v = al.ld(bz, m0 + r, kt + c4);
            As[c4 + 0][r] = v.x; As[c4 + 1][r] = v.y;
            As[c4 + 2][r] = v.z; As[c4 + 3][r] = v.w;
        }
        if constexpr (!BL::kTrans) {
            #pragma unroll
            for (int i = 0; i < 2; i++) {
                int f = tid + i * 256;
                int r = f >> 5, c4 = (f & 31) * 4;
                float4 v = bl.ld(bz, kt + r, n0 + c4);
                *reinterpret_cast<float4*>(&Bs[r][c4]) = v;
            }
        } else {
            #pragma unroll
            for (int i = 0; i < 2; i++) {
                int f = tid + i * 256;
                int r = f >> 2, c4 = (f & 3) * 4;
                float4 v = bl.ld(bz, n0 + r, kt + c4);
                Bs[c4 + 0][r] = v.x; Bs[c4 + 1][r] = v.y;
                Bs[c4 + 2][r] = v.z; Bs[c4 + 3][r] = v.w;
            }
        }
        __syncthreads();
        #pragma unroll
        for (int kk = 0; kk < BK; kk++) {
            float a[TM], b[TN];
            *reinterpret_cast<float4*>(&a[0]) = *reinterpret_cast<const float4*>(&As[kk][ty * TM]);
            *reinterpret_cast<float4*>(&a[4]) = *reinterpret_cast<const float4*>(&As[kk][ty * TM + 4]);
            *reinterpret_cast<float4*>(&b[0]) = *reinterpret_cast<const float4*>(&Bs[kk][tx * TN]);
            *reinterpret_cast<float4*>(&b[4]) = *reinterpret_cast<const float4*>(&Bs[kk][tx * TN + 4]);
            #pragma unroll
            for (int i = 0; i < TM; i++)
                #pragma unroll
                for (int j = 0; j < TN; j++)
                    acc[i][j] = fmaf(a[i], b[j], acc[i][j]);
        }
        __syncthreads();
    }

    #pragma unroll
    for (int i = 0; i < TM; i++) {
        int row = m0 + ty * TM + i;
        #pragma unroll
        for (int j = 0; j < TN; j++) {
            int col = n0 + tx * TN + j;
            ep.store(bz, row, col, acc[i][j]);
        }
    }
}

// ---------------- launch ----------------
extern "C" void kernel_launch(void* const* d_in, const int* in_sizes, int n_in,
                              void* d_out, int out_size)
{
    const float* x        = (const float*)d_in[0];
    const float* delta    = (const float*)d_in[1];
    const float* alpha    = (const float*)d_in[2];
    const float* beta_ema = (const float*)d_in[3];
    const float* gamma_e  = (const float*)d_in[4];
    const float* omega    = (const float*)d_in[5];
    const float* v_w      = (const float*)d_in[6];
    const float* v_b      = (const float*)d_in[7];
    const float* mx_w     = (const float*)d_in[8];
    const float* mx_b     = (const float*)d_in[9];
    const float* h_w      = (const float*)d_in[10];
    const float* h_b      = (const float*)d_in[11];
    const float* qk_gamma = (const float*)d_in[12];
    const float* qk_beta  = (const float*)d_in[13];
    const float* rel_pos  = (const float*)d_in[14];
    const float* ln_w     = (const float*)d_in[15];
    const float* ln_b     = (const float*)d_in[16];
    float* out = (float*)d_out;

    // 1. layernorm
    ln_kernel<<<ROWS, 256>>>(x, ln_w, ln_b);

    // 2. EMA: param precompute + 3-pass chunked scan
    ema_pre<<<(Dd * Nn + 255) / 256, 256>>>(delta, alpha, beta_ema, gamma_e);
    ema_scanA<<<(Bc * Dd * NC) / 256, 256>>>();
    ema_scanB<<<(Bc * Dd * Nn) / 256, 256>>>();
    ema_scanC<<<(Bc * Dd * NC) / 256, 256>>>(omega);

    // 3. v = silu(xn @ v_w + v_b)
    gemm_k<<<dim3(Hh / BN, ROWS / BM, 1), 256>>>(ALxn{}, BLnn{v_w, Hh}, EPv{v_b}, Dd);

    // 4. base = mx @ mx_w + mx_b  -> u / q,k / r / hx  (router epilogue)
    gemm_k<<<dim3(NMX / BN, ROWS / BM, 1), 256>>>(ALmx{}, BLnn{mx_w, NMX},
                                                  EPmx{mx_b, qk_gamma, qk_beta}, Dd);

    // 5. attn = laplace(q k^T / L + bias)   (batched, B tensor transposed)
    gemm_k<<<dim3(Lx / BN, Lx / BM, Bc), 256>>>(ALq{}, BLkT{}, EPqk{rel_pos}, Zz);

    // 6. h = attn @ v   (batched)
    gemm_k<<<dim3(Hh / BN, Lx / BM, Bc), 256>>>(ALattn{}, BLv{}, EPav{}, Lx);

    // 7. out = x + u * (silu(hx + (h*r) @ h_w + h_b) - x)
    gemm_k<<<dim3(Dd / BN, ROWS / BM, 1), 256>>>(ALhr{}, BLnn{h_w, Dd}, EPf{h_b, x, out}, Hh);
}

// round 4
// speedup vs baseline: 2.1954x; 2.1954x over previous
#include <cuda_runtime.h>
#include <math.h>
#include <stdint.h>

#define DEV __device__ __forceinline__

// ---------------- problem constants ----------------
constexpr int Lx = 2048, Bc = 8, Dd = 1024, Zz = 128, Hh = 2048, Nn = 16;
constexpr int ROWS = Lx * Bc;                 // 16384
constexpr int NMX  = Dd + Zz + Hh + Dd;       // 4224
constexpr int NMXP = 4352;                    // padded to 34*128
constexpr int NC   = 16, CL = Lx / NC;        // 16 chunks x 128 steps
constexpr float LAP_MU  = 0.707107f;
constexpr float LAP_INV = 1.0f / (0.282095f * 1.41421356237f);

// ---------------- device scratch ----------------
__device__ __align__(16) float g_xn  [ROWS * Dd];
__device__ __align__(16) float g_mx  [ROWS * Dd];
__device__ __align__(16) float g_vT  [Bc * Hh * Lx];     // v transposed [b][h][l]
__device__ __align__(16) float g_u   [ROWS * Dd];
__device__ __align__(16) float g_hx  [ROWS * Dd];
__device__ __align__(16) float g_r   [ROWS * Hh];
__device__ __align__(16) float g_q   [Bc * Lx * Zz];
__device__ __align__(16) float g_k   [Bc * Lx * Zz];
__device__ __align__(16) float g_attn[Bc * Lx * Lx];
__device__ __align__(16) float g_hatt[Bc * Lx * Hh];
__device__ __align__(16) float g_vwT [Hh * Dd];          // v_w^T  [n=h][k=d]
__device__ __align__(16) float g_mxwT[NMXP * Dd];        // mx_w^T padded
__device__ __align__(16) float g_hwT [Dd * Hh];          // h_w^T  [n=d][k=h]
__device__ float g_eq   [Nn * Dd];
__device__ float g_ew   [Nn * Dd];
__device__ float g_eq128[Nn * Dd];
__device__ float g_send [Bc * Dd * NC * Nn];
__device__ float g_carry[Bc * Dd * NC * Nn];

DEV float sigm(float x)  { return 1.0f / (1.0f + expf(-x)); }
DEV float silu(float x)  { return x / (1.0f + expf(-x)); }
DEV uint32_t to_tf32(float x) {
    uint32_t u;
    asm("cvt.rna.tf32.f32 %0, %1;" : "=r"(u) : "f"(x));
    return u;
}
// chunk swizzle: XOR bits [4:2] of chunk index into bits [2:0] (bijective within 8-chunk blocks)
DEV uint32_t swz(uint32_t c) { return c ^ ((c >> 2) & 7u); }

// ---------------- layernorm ----------------
__global__ void ln_kernel(const float* __restrict__ x,
                          const float* __restrict__ w,
                          const float* __restrict__ b)
{
    int row = blockIdx.x;
    const float4* xr = reinterpret_cast<const float4*>(x + (size_t)row * Dd);
    float4 v = xr[threadIdx.x];
    float s  = v.x + v.y + v.z + v.w;
    float s2 = v.x*v.x + v.y*v.y + v.z*v.z + v.w*v.w;
    #pragma unroll
    for (int o = 16; o; o >>= 1) {
        s  += __shfl_xor_sync(0xffffffffu, s,  o);
        s2 += __shfl_xor_sync(0xffffffffu, s2, o);
    }
    __shared__ float sh[16];
    int warp = threadIdx.x >> 5, lane = threadIdx.x & 31;
    if (lane == 0) { sh[warp] = s; sh[8 + warp] = s2; }
    __syncthreads();
    float S = 0.f, S2 = 0.f;
    #pragma unroll
    for (int i = 0; i < 8; i++) { S += sh[i]; S2 += sh[8 + i]; }
    float mu  = S * (1.0f / Dd);
    float var = S2 * (1.0f / Dd) - mu * mu;
    float rs  = rsqrtf(var + 1e-5f);
    float4 wv = reinterpret_cast<const float4*>(w)[threadIdx.x];
    float4 bv = reinterpret_cast<const float4*>(b)[threadIdx.x];
    float4 o;
    o.x = (v.x - mu) * rs * wv.x + bv.x;
    o.y = (v.y - mu) * rs * wv.y + bv.y;
    o.z = (v.z - mu) * rs * wv.z + bv.z;
    o.w = (v.w - mu) * rs * wv.w + bv.w;
    reinterpret_cast<float4*>(g_xn + (size_t)row * Dd)[threadIdx.x] = o;
}

// ---------------- EMA ----------------
__global__ void ema_pre(const float* __restrict__ delta, const float* __restrict__ alpha,
                        const float* __restrict__ beta,  const float* __restrict__ gamma)
{
    int i = blockIdx.x * 256 + threadIdx.x;
    if (i >= Dd * Nn) return;
    int d = i / Nn, n = i % Nn;
    float p = sigm(delta[i]);
    float q = 1.0f - p * sigm(alpha[i]);
    float w = p * beta[i] * gamma[i] * 0.25f;
    float qq = q;
    #pragma unroll
    for (int t = 0; t < 7; t++) qq *= qq;
    g_eq   [n * Dd + d] = q;
    g_ew   [n * Dd + d] = w;
    g_eq128[n * Dd + d] = qq;
}

__global__ void ema_scanA()
{
    int g = blockIdx.x * 256 + threadIdx.x;
    int d = g & (Dd - 1);
    int rest = g >> 10;
    int b = rest & (Bc - 1);
    int c = rest >> 3;
    float q[Nn], s[Nn];
    #pragma unroll
    for (int n = 0; n < Nn; n++) { q[n] = g_eq[n * Dd + d]; s[n] = 0.f; }
    const float* xp = g_xn + ((size_t)(c * CL) * Bc + b) * Dd + d;
    const size_t stride = (size_t)Bc * Dd;
    for (int i = 0; i < CL; i++) {
        float xv = xp[i * stride];
        #pragma unroll
        for (int n = 0; n < Nn; n++) s[n] = fmaf(q[n], s[n], xv);
    }
    float* o = g_send + ((size_t)(b * Dd + d) * NC + c) * Nn;
    #pragma unroll
    for (int n = 0; n < Nn; n++) o[n] = s[n];
}

__global__ void ema_scanB()
{
    int g = blockIdx.x * 256 + threadIdx.x;
    int n = g & (Nn - 1);
    int rest = g >> 4;
    int d = rest & (Dd - 1);
    int b = rest >> 10;
    float q128 = g_eq128[n * Dd + d];
    size_t base = (size_t)(b * Dd + d) * NC * Nn + n;
    float cur = 0.f;
    for (int c = 0; c < NC; c++) {
        g_carry[base + (size_t)c * Nn] = cur;
        cur = fmaf(q128, cur, g_send[base + (size_t)c * Nn]);
    }
}

__global__ void ema_scanC(const float* __restrict__ omega)
{
    int g = blockIdx.x * 256 + threadIdx.x;
    int d = g & (Dd - 1);
    int rest = g >> 10;
    int b = rest & (Bc - 1);
    int c = rest >> 3;
    float q[Nn], w[Nn], s[Nn];
    const float* cp = g_carry + ((size_t)(b * Dd + d) * NC + c) * Nn;
    #pragma unroll
    for (int n = 0; n < Nn; n++) {
        q[n] = g_eq[n * Dd + d];
        w[n] = g_ew[n * Dd + d];
        s[n] = cp[n];
    }
    float om = omega[d];
    const size_t stride = (size_t)Bc * Dd;
    const float* xp = g_xn + ((size_t)(c * CL) * Bc + b) * Dd + d;
    float*       mp = g_mx + ((size_t)(c * CL) * Bc + b) * Dd + d;
    for (int i = 0; i < CL; i++) {
        float xv = xp[i * stride];
        #pragma unroll
        for (int n = 0; n < Nn; n++) s[n] = fmaf(q[n], s[n], xv);
        float o0 = 0.f, o1 = 0.f, o2 = 0.f, o3 = 0.f;
        #pragma unroll
        for (int n = 0; n < Nn; n++) {
            float t = w[n] * s[n];
            if ((n & 3) == 0) o0 += t; else if ((n & 3) == 1) o1 += t;
            else if ((n & 3) == 2) o2 += t; else o3 += t;
        }
        float val = (o0 + o1) + (o2 + o3) + xv * om;
        mp[i * stride] = silu(val);
    }
}

// ---------------- weight transpose (K x N -> Npad x K, zero-pad) ----------------
__global__ void transpose_w(const float* __restrict__ src, float* __restrict__ dst,
                            int K, int N, int Npad)
{
    __shared__ float t[32][33];
    int n0 = blockIdx.x * 32, k0 = blockIdx.y * 32;
    int tx = threadIdx.x, ty = threadIdx.y;
    #pragma unroll
    for (int j = 0; j < 32; j += 8) {
        int k = k0 + ty + j, n = n0 + tx;
        t[ty + j][tx] = (n < N) ? src[(size_t)k * N + n] : 0.f;
    }
    __syncthreads();
    #pragma unroll
    for (int j = 0; j < 32; j += 8) {
        int n = n0 + ty + j, k = k0 + tx;
        if (n < Npad) dst[(size_t)n * K + k] = t[tx][ty + j];
    }
}

// ---------------- operand loaders (all K-contiguous float4) ----------------
struct ALxn {
    DEV float4 ld(int, int r, int k) const {
        return *reinterpret_cast<const float4*>(g_xn + (size_t)r * Dd + k);
    }
};
struct ALmx {
    DEV float4 ld(int, int r, int k) const {
        return *reinterpret_cast<const float4*>(g_mx + (size_t)r * Dd + k);
    }
};
struct ALq {
    DEV float4 ld(int bz, int r, int k) const {
        return *reinterpret_cast<const float4*>(g_q + ((size_t)bz * Lx + r) * Zz + k);
    }
};
struct ALattn {
    DEV float4 ld(int bz, int r, int k) const {
        return *reinterpret_cast<const float4*>(g_attn + ((size_t)bz * Lx + r) * Lx + k);
    }
};
struct ALhr {
    DEV float4 ld(int, int row, int k) const {
        int l = row >> 3, b = row & 7;
        float4 hv = *reinterpret_cast<const float4*>(g_hatt + ((size_t)b * Lx + l) * Hh + k);
        float4 rv = *reinterpret_cast<const float4*>(g_r + (size_t)row * Hh + k);
        return make_float4(hv.x * rv.x, hv.y * rv.y, hv.z * rv.z, hv.w * rv.w);
    }
};
struct BLvw {
    DEV float4 ld(int, int n, int k) const {
        return *reinterpret_cast<const float4*>(g_vwT + (size_t)n * Dd + k);
    }
};
struct BLmxw {
    DEV float4 ld(int, int n, int k) const {
        return *reinterpret_cast<const float4*>(g_mxwT + (size_t)n * Dd + k);
    }
};
struct BLhw {
    DEV float4 ld(int, int n, int k) const {
        return *reinterpret_cast<const float4*>(g_hwT + (size_t)n * Hh + k);
    }
};
struct BLkm {
    DEV float4 ld(int bz, int n, int k) const {
        return *reinterpret_cast<const float4*>(g_k + ((size_t)bz * Lx + n) * Zz + k);
    }
};
struct BLvT {
    DEV float4 ld(int bz, int n, int k) const {
        return *reinterpret_cast<const float4*>(g_vT + ((size_t)bz * Hh + n) * Lx + k);
    }
};

// ---------------- epilogues ----------------
struct EPv {   // silu, store transposed vT[b][h][l]
    const float* vb;
    DEV void store(int, int row, int col, float a) const {
        int l = row >> 3, b = row & 7;
        g_vT[((size_t)b * Hh + col) * Lx + l] = silu(a + vb[col]);
    }
};
struct EPmx {
    const float* mxb; const float* qg; const float* qb;
    DEV void store(int, int row, int col, float a) const {
        if (col >= NMX) return;
        float val = a + mxb[col];
        if (col < Dd) {
            g_u[(size_t)row * Dd + col] = sigm(val);
        } else if (col < Dd + Zz) {
            int z = col - Dd;
            float s = silu(val);
            int l = row >> 3, b = row & 7;
            size_t o = ((size_t)b * Lx + l) * Zz + z;
            g_q[o] = s * qg[z]      + qb[z];
            g_k[o] = s * qg[Zz + z] + qb[Zz + z];
        } else if (col < Dd + Zz + Hh) {
            g_r[(size_t)row * Hh + (col - Dd - Zz)] = silu(val);
        } else {
            g_hx[(size_t)row * Dd + (col - Dd - Zz - Hh)] = val;
        }
    }
};
struct EPqk {
    const float* rel;
    DEV void store(int bz, int l, int m, float a) const {
        float x = a * (1.0f / (float)Lx) + rel[2047 + m - l];
        g_attn[((size_t)bz * Lx + l) * Lx + m] =
            0.5f * (1.0f + erff((x - LAP_MU) * LAP_INV));
    }
};
struct EPav {
    DEV void store(int bz, int l, int h, float a) const {
        g_hatt[((size_t)bz * Lx + l) * Hh + h] = a;
    }
};
struct EPf {
    const float* hb; const float* x; float* out;
    DEV void store(int, int row, int col, float a) const {
        size_t o = (size_t)row * Dd + col;
        float hval = silu(g_hx[o] + a + hb[col]);
        float xv = x[o];
        out[o] = xv + g_u[o] * (hval - xv);
    }
};

// ---------------- mma.sync tf32 GEMM: 128x128 tile, BK=16, 8 warps ----------------
// smem fragment-major layout:
//   A: chunk16B index (mf*2+ks)*32 + lane; 4 words = a0..a3  (8KB/buffer)
//   B: chunk8B  index (nf*2+ks)*32 + lane; 2 words = b0,b1   (8KB/buffer)
// both chunk-swizzled with swz() for conflict-free fragment loads.
DEV void mma_tf32(float* c, const uint32_t* a, const uint32_t* b) {
    asm volatile(
        "mma.sync.aligned.m16n8k8.row.col.f32.tf32.tf32.f32 "
        "{%0,%1,%2,%3}, {%4,%5,%6,%7}, {%8,%9}, {%0,%1,%2,%3};"
        : "+f"(c[0]), "+f"(c[1]), "+f"(c[2]), "+f"(c[3])
        : "r"(a[0]), "r"(a[1]), "r"(a[2]), "r"(a[3]), "r"(b[0]), "r"(b[1]));
}

template <class AL, class BL, class EP>
__global__ __launch_bounds__(256, 2)
void mma_gemm(AL al, BL bl, EP ep, int K)
{
    __shared__ uint32_t As[2][2048];
    __shared__ uint32_t Bs[2][2048];

    const int tid  = threadIdx.x;
    const int lane = tid & 31, wid = tid >> 5;
    const int warpM = wid & 1, warpN = wid >> 1;      // 2 x 4 warps
    const int bz = blockIdx.z;
    const int m0 = blockIdx.y * 128, n0 = blockIdx.x * 128;

    // global-load coords for this thread (2 float4 per tile, each covers (r, c*4..c*4+3))
    const int r0g = tid >> 2,  c0g = tid & 3;          // f = 0
    const int r1g = r0g + 64;                          // f = 1 (idx + 256)

    // scatter-store precomputed pieces: lane slot = g*4 + j, v = (c&1)*2 + half (A), v = c&1 (B)
    auto stA = [&](int buf, int r, int c, float4 v) {
        int mf = r >> 4, rr = r & 15, g = rr & 7, half = rr >> 3;
        int ks = c >> 1, vv = (c & 1) * 2 + half;
        uint32_t base = (uint32_t)((mf * 2 + ks) * 32 + g * 4);
        #pragma unroll
        for (int j = 0; j < 4; j++) {
            float e = (j == 0) ? v.x : (j == 1) ? v.y : (j == 2) ? v.z : v.w;
            As[buf][swz(base + j) * 4 + vv] = to_tf32(e);
        }
    };
    auto stB = [&](int buf, int r, int c, float4 v) {
        int nf = r >> 3, g = r & 7;
        int ks = c >> 1, vv = c & 1;
        uint32_t base = (uint32_t)((nf * 2 + ks) * 32 + g * 4);
        #pragma unroll
        for (int j = 0; j < 4; j++) {
            float e = (j == 0) ? v.x : (j == 1) ? v.y : (j == 2) ? v.z : v.w;
            Bs[buf][swz(base + j) * 2 + vv] = to_tf32(e);
        }
    };

    float acc[4][4][4] = {};

    const int nit = K >> 4;

    // prologue: load + store k-tile 0
    {
        float4 a0 = al.ld(bz, m0 + r0g, c0g * 4);
        float4 a1 = al.ld(bz, m0 + r1g, c0g * 4);
        float4 b0 = bl.ld(bz, n0 + r0g, c0g * 4);
        float4 b1 = bl.ld(bz, n0 + r1g, c0g * 4);
        stA(0, r0g, c0g, a0); stA(0, r1g, c0g, a1);
        stB(0, r0g, c0g, b0); stB(0, r1g, c0g, b1);
    }
    __syncthreads();

    for (int it = 0; it < nit; ++it) {
        const int buf = it & 1;

        // prefetch next k-tile into registers
        float4 na0, na1, nb0, nb1;
        if (it + 1 < nit) {
            int kt = (it + 1) << 4;
            na0 = al.ld(bz, m0 + r0g, kt + c0g * 4);
            na1 = al.ld(bz, m0 + r1g, kt + c0g * 4);
            nb0 = bl.ld(bz, n0 + r0g, kt + c0g * 4);
            nb1 = bl.ld(bz, n0 + r1g, kt + c0g * 4);
        }

        // compute on buf
        #pragma unroll
        for (int ks = 0; ks < 2; ks++) {
            uint32_t af[4][4];
            uint32_t bf[4][2];
            #pragma unroll
            for (int i = 0; i < 4; i++) {
                int mf = warpM * 4 + i;
                uint32_t ch = swz((uint32_t)((mf * 2 + ks) * 32 + lane));
                uint4 t = *reinterpret_cast<const uint4*>(&As[buf][ch * 4]);
                af[i][0] = t.x; af[i][1] = t.y; af[i][2] = t.z; af[i][3] = t.w;
            }
            #pragma unroll
            for (int j = 0; j < 4; j++) {
                int nf = warpN * 4 + j;
                uint32_t ch = swz((uint32_t)((nf * 2 + ks) * 32 + lane));
                uint2 t = *reinterpret_cast<const uint2*>(&Bs[buf][ch * 2]);
                bf[j][0] = t.x; bf[j][1] = t.y;
            }
            #pragma unroll
            for (int i = 0; i < 4; i++)
                #pragma unroll
                for (int j = 0; j < 4; j++)
                    mma_tf32(acc[i][j], af[i], bf[j]);
        }

        if (it + 1 < nit) {
            __syncthreads();                       // everyone done reading buf^1
            stA(buf ^ 1, r0g, c0g, na0); stA(buf ^ 1, r1g, c0g, na1);
            stB(buf ^ 1, r0g, c0g, nb0); stB(buf ^ 1, r1g, c0g, nb1);
            __syncthreads();                       // stores visible
        }
    }

    // epilogue: acc -> ep.store
    const int mw = m0 + warpM * 64, nw = n0 + warpN * 32;
    const int rl = lane >> 2, cl = (lane & 3) * 2;
    #pragma unroll
    for (int i = 0; i < 4; i++) {
        int ra = mw + i * 16 + rl;
        #pragma unroll
        for (int j = 0; j < 4; j++) {
            int cc = nw + j * 8 + cl;
            ep.store(bz, ra,     cc,     acc[i][j][0]);
            ep.store(bz, ra,     cc + 1, acc[i][j][1]);
            ep.store(bz, ra + 8, cc,     acc[i][j][2]);
            ep.store(bz, ra + 8, cc + 1, acc[i][j][3]);
        }
    }
}

// ---------------- launch ----------------
extern "C" void kernel_launch(void* const* d_in, const int* in_sizes, int n_in,
                              void* d_out, int out_size)
{
    const float* x        = (const float*)d_in[0];
    const float* delta    = (const float*)d_in[1];
    const float* alpha    = (const float*)d_in[2];
    const float* beta_ema = (const float*)d_in[3];
    const float* gamma_e  = (const float*)d_in[4];
    const float* omega    = (const float*)d_in[5];
    const float* v_w      = (const float*)d_in[6];
    const float* v_b      = (const float*)d_in[7];
    const float* mx_w     = (const float*)d_in[8];
    const float* mx_b     = (const float*)d_in[9];
    const float* h_w      = (const float*)d_in[10];
    const float* h_b      = (const float*)d_in[11];
    const float* qk_gamma = (const float*)d_in[12];
    const float* qk_beta  = (const float*)d_in[13];
    const float* rel_pos  = (const float*)d_in[14];
    const float* ln_w     = (const float*)d_in[15];
    const float* ln_b     = (const float*)d_in[16];
    float* out = (float*)d_out;

    // weight transposes (independent of ln/ema)
    float* vwT  = nullptr; float* mxwT = nullptr; float* hwT = nullptr;
    cudaGetSymbolAddress((void**)&vwT,  g_vwT);
    cudaGetSymbolAddress((void**)&mxwT, g_mxwT);
    cudaGetSymbolAddress((void**)&hwT,  g_hwT);
    transpose_w<<<dim3(Hh / 32,   Dd / 32), dim3(32, 8)>>>(v_w,  vwT,  Dd, Hh,  Hh);
    transpose_w<<<dim3(NMXP / 32, Dd / 32), dim3(32, 8)>>>(mx_w, mxwT, Dd, NMX, NMXP);
    transpose_w<<<dim3(Dd / 32,   Hh / 32), dim3(32, 8)>>>(h_w,  hwT,  Hh, Dd,  Dd);

    // 1. layernorm
    ln_kernel<<<ROWS, 256>>>(x, ln_w, ln_b);

    // 2. EMA chunked scan
    ema_pre<<<(Dd * Nn + 255) / 256, 256>>>(delta, alpha, beta_ema, gamma_e);
    ema_scanA<<<(Bc * Dd * NC) / 256, 256>>>();
    ema_scanB<<<(Bc * Dd * Nn) / 256, 256>>>();
    ema_scanC<<<(Bc * Dd * NC) / 256, 256>>>(omega);

    // 3. v = silu(xn @ v_w + v_b), stored transposed
    mma_gemm<<<dim3(Hh / 128, ROWS / 128, 1), 256>>>(ALxn{}, BLvw{}, EPv{v_b}, Dd);

    // 4. base = mx @ mx_w + mx_b -> u / q,k / r / hx
    mma_gemm<<<dim3(NMXP / 128, ROWS / 128, 1), 256>>>(ALmx{}, BLmxw{},
                                                       EPmx{mx_b, qk_gamma, qk_beta}, Dd);

    // 5. attn = laplace(q k^T / L + bias)
    mma_gemm<<<dim3(Lx / 128, Lx / 128, Bc), 256>>>(ALq{}, BLkm{}, EPqk{rel_pos}, Zz);

    // 6. h = attn @ v
    mma_gemm<<<dim3(Hh / 128, Lx / 128, Bc), 256>>>(ALattn{}, BLvT{}, EPav{}, Lx);

    // 7. out = x + u * (silu(hx + (h*r) @ h_w + h_b) - x)
    mma_gemm<<<dim3(Dd / 128, ROWS / 128, 1), 256>>>(ALhr{}, BLhw{}, EPf{h_b, x, out}, Hh);
}